// round 13
// baseline (speedup 1.0000x reference)
#include <cuda_runtime.h>
#include <cuda_fp16.h>
#include <math.h>
#include <stdint.h>

#define D_    768
#define H_    12
#define HD_   64
#define DFF_  3072
#define MAXT  8192
#define SMAX_ 1024

// ---------------- scratch (no allocations allowed) ----------------
__device__ __half g_xnh  [(size_t)MAXT * D_];
__device__ __half g_qkvh [(size_t)MAXT * 3 * D_];
__device__ __half g_attnh[(size_t)MAXT * D_];
__device__ float  g_x2   [(size_t)MAXT * D_];
__device__ __half g_midh [(size_t)MAXT * DFF_];
__device__ __half g_WqkvTh[(size_t)3 * D_ * D_];
__device__ __half g_WoTh  [(size_t)D_ * D_];
__device__ __half g_W1Th  [(size_t)DFF_ * D_];
__device__ __half g_W2Th  [(size_t)D_ * DFF_];

// ---------------- helpers ----------------
__device__ __forceinline__ uint32_t smem_u32(const void* p) {
    uint32_t a;
    asm("{ .reg .u64 t; cvta.to.shared.u64 t, %1; cvt.u32.u64 %0, t; }" : "=r"(a) : "l"(p));
    return a;
}
#define CP_ASYNC16(dst, src) \
    asm volatile("cp.async.cg.shared.global [%0], [%1], 16;" :: "r"(dst), "l"(src) : "memory")
#define CP_ASYNC16Z(dst, src) \
    asm volatile("cp.async.cg.shared.global [%0], [%1], 16, 0;" :: "r"(dst), "l"(src) : "memory")
#define CP_COMMIT() asm volatile("cp.async.commit_group;" ::: "memory")
#define CP_WAIT(n)  asm volatile("cp.async.wait_group %0;" :: "n"(n) : "memory")

__device__ __forceinline__ void mma_f16(float* c, const uint32_t* a, const uint32_t* b) {
    asm volatile(
        "mma.sync.aligned.m16n8k16.row.col.f32.f16.f16.f32 "
        "{%0,%1,%2,%3}, {%4,%5,%6,%7}, {%8,%9}, {%0,%1,%2,%3};"
        : "+f"(c[0]), "+f"(c[1]), "+f"(c[2]), "+f"(c[3])
        : "r"(a[0]), "r"(a[1]), "r"(a[2]), "r"(a[3]), "r"(b[0]), "r"(b[1]));
}
__device__ __forceinline__ void ldsm_x2_t(uint32_t& r0, uint32_t& r1, uint32_t a) {
    asm volatile("ldmatrix.sync.aligned.m8n8.x2.trans.shared.b16 {%0,%1}, [%2];"
                 : "=r"(r0), "=r"(r1) : "r"(a));
}
__device__ __forceinline__ uint32_t h2u(float a, float b) {
    __half2 t = __floats2half2_rn(a, b);
    return *(uint32_t*)&t;
}

// ---------------- transpose + fp16 round ----------------
__global__ void __launch_bounds__(256) transpose_h(const float* __restrict__ W,
                                                   __half* __restrict__ WT,
                                                   int K, int N) {
    __shared__ float tile[32][33];
    int tx = threadIdx.x, ty = threadIdx.y;
    int n0 = blockIdx.x * 32, k0 = blockIdx.y * 32;
#pragma unroll
    for (int i = 0; i < 4; i++)
        tile[ty + 8 * i][tx] = W[(size_t)(k0 + ty + 8 * i) * N + n0 + tx];
    __syncthreads();
#pragma unroll
    for (int i = 0; i < 4; i++)
        WT[(size_t)(n0 + ty + 8 * i) * K + k0 + tx] = __float2half(tile[tx][ty + 8 * i]);
}

// ---------------- LayerNorm (warp-shuffle reduction, fp16 output) ----------------
__global__ void __launch_bounds__(256) ln_kernel(const float* __restrict__ x,
                                                 const float* __restrict__ g,
                                                 const float* __restrict__ be,
                                                 __half* __restrict__ y) {
    int t = blockIdx.x;
    const float* xr = x + (size_t)t * D_;
    __half*      yr = y + (size_t)t * D_;
    int tid  = threadIdx.x;
    int lane = tid & 31, warp = tid >> 5;
    float v0 = xr[tid], v1 = xr[tid + 256], v2 = xr[tid + 512];
    float s  = v0 + v1 + v2;
    float s2 = v0 * v0 + v1 * v1 + v2 * v2;
#pragma unroll
    for (int off = 16; off >= 1; off >>= 1) {
        s  += __shfl_xor_sync(0xffffffffu, s,  off);
        s2 += __shfl_xor_sync(0xffffffffu, s2, off);
    }
    __shared__ float w1[8], w2[8], bc[2];
    if (lane == 0) { w1[warp] = s; w2[warp] = s2; }
    __syncthreads();
    if (warp == 0) {
        float a = (lane < 8) ? w1[lane] : 0.f;
        float b = (lane < 8) ? w2[lane] : 0.f;
#pragma unroll
        for (int off = 4; off >= 1; off >>= 1) {
            a += __shfl_xor_sync(0xffffffffu, a, off);
            b += __shfl_xor_sync(0xffffffffu, b, off);
        }
        if (lane == 0) {
            float mu  = a * (1.0f / D_);
            float var = b * (1.0f / D_) - mu * mu;
            bc[0] = mu;
            bc[1] = rsqrtf(var + 1e-6f);
        }
    }
    __syncthreads();
    float mu = bc[0], r = bc[1];
    yr[tid]       = __float2half((v0 - mu) * r * g[tid]       + be[tid]);
    yr[tid + 256] = __float2half((v1 - mu) * r * g[tid + 256] + be[tid + 256]);
    yr[tid + 512] = __float2half((v2 - mu) * r * g[tid + 512] + be[tid + 512]);
}

// ---------------- fp16 mma.sync GEMM: K-chunk 64, 2-stage ring ----------------
// CTA 128x128, 128 threads, 4 warps (2x2), warp tile 64x64.
// Row stride 72 halves (144B): cp.async 16B-aligned, conflict-free frag LDS.
#define TSH   72
#define STG_H (128 * TSH)
template <int EPI, typename OutT>
__global__ void __launch_bounds__(128) tgemm(const __half* __restrict__ A,
                                             const __half* __restrict__ BT,
                                             const float* __restrict__ bias,
                                             const float* __restrict__ res,
                                             OutT* __restrict__ C,
                                             int M, int N, int K) {
    extern __shared__ __half smh[];
    __half* As = smh;                      // [2][STG_H]
    __half* Bs = smh + 2 * STG_H;          // [2][STG_H]

    int tid = threadIdx.x;
    int lane = tid & 31, wid = tid >> 5;
    int warpM = wid >> 1, warpN = wid & 1;
    int g = lane >> 2, t4 = lane & 3;
    int bm = blockIdx.y * 128, bn = blockIdx.x * 128;

    const __half* gA = A  + (size_t)bm * K;
    const __half* gB = BT + (size_t)bn * K;

    int lrow = tid >> 3;                   // 0..15 (+16i)
    int c16  = tid & 7;                    // 16B group within 64-half chunk row

    float acc[4][8][4];
#pragma unroll
    for (int mf = 0; mf < 4; mf++)
#pragma unroll
        for (int nf = 0; nf < 8; nf++)
#pragma unroll
            for (int r = 0; r < 4; r++) acc[mf][nf][r] = 0.f;

    uint32_t sA0 = smem_u32(As), sB0 = smem_u32(Bs);
    int nc = K >> 6;

    auto issue = [&](int c, int s) {
        uint32_t sa = sA0 + (uint32_t)s * STG_H * 2;
        uint32_t sb = sB0 + (uint32_t)s * STG_H * 2;
        const __half* a0 = gA + (c << 6) + c16 * 8;
        const __half* b0 = gB + (c << 6) + c16 * 8;
#pragma unroll
        for (int i = 0; i < 8; i++) {
            int row = lrow + 16 * i;
            uint32_t off = (uint32_t)(row * TSH + c16 * 8) * 2;
            CP_ASYNC16(sa + off, a0 + (size_t)row * K);
            CP_ASYNC16(sb + off, b0 + (size_t)row * K);
        }
        CP_COMMIT();
    };

    issue(0, 0);

    for (int c = 0; c < nc; c++) {
        CP_WAIT(0);
        __syncthreads();
        if (c + 1 < nc) issue(c + 1, (c + 1) & 1);

        const __half* as = As + (c & 1) * STG_H;
        const __half* bs = Bs + (c & 1) * STG_H;
#pragma unroll
        for (int ko = 0; ko < 64; ko += 16) {
            uint32_t af[4][4];
#pragma unroll
            for (int mf = 0; mf < 4; mf++) {
                int r = warpM * 64 + mf * 16 + g;
                af[mf][0] = *(const uint32_t*)&as[r * TSH + ko + 2 * t4];
                af[mf][1] = *(const uint32_t*)&as[(r + 8) * TSH + ko + 2 * t4];
                af[mf][2] = *(const uint32_t*)&as[r * TSH + ko + 2 * t4 + 8];
                af[mf][3] = *(const uint32_t*)&as[(r + 8) * TSH + ko + 2 * t4 + 8];
            }
            uint32_t bf[8][2];
#pragma unroll
            for (int nf = 0; nf < 8; nf++) {
                int n = warpN * 64 + nf * 8 + g;
                bf[nf][0] = *(const uint32_t*)&bs[n * TSH + ko + 2 * t4];
                bf[nf][1] = *(const uint32_t*)&bs[n * TSH + ko + 2 * t4 + 8];
            }
#pragma unroll
            for (int mf = 0; mf < 4; mf++)
#pragma unroll
                for (int nf = 0; nf < 8; nf++)
                    mma_f16(acc[mf][nf], af[mf], bf[nf]);
        }
    }

#pragma unroll
    for (int mf = 0; mf < 4; mf++) {
        int r0 = bm + warpM * 64 + mf * 16 + g;
#pragma unroll
        for (int nf = 0; nf < 8; nf++) {
            int cc = bn + warpN * 64 + nf * 8 + t4 * 2;
            float b0 = bias[cc], b1 = bias[cc + 1];
            float v00 = acc[mf][nf][0] + b0, v01 = acc[mf][nf][1] + b1;
            float v10 = acc[mf][nf][2] + b0, v11 = acc[mf][nf][3] + b1;
            if (EPI == 1) {
                const float* rp0 = res + (size_t)r0 * N + cc;
                const float* rp1 = res + (size_t)(r0 + 8) * N + cc;
                v00 += rp0[0]; v01 += rp0[1];
                v10 += rp1[0]; v11 += rp1[1];
            }
            if (EPI == 2) {
                v00 = 0.5f * v00 * (1.0f + erff(v00 * 0.70710678118654752f));
                v01 = 0.5f * v01 * (1.0f + erff(v01 * 0.70710678118654752f));
                v10 = 0.5f * v10 * (1.0f + erff(v10 * 0.70710678118654752f));
                v11 = 0.5f * v11 * (1.0f + erff(v11 * 0.70710678118654752f));
            }
            if (sizeof(OutT) == 2) {
                __half2 h0 = __floats2half2_rn(v00, v01);
                __half2 h1 = __floats2half2_rn(v10, v11);
                *(__half2*)((__half*)C + (size_t)r0 * N + cc)       = h0;
                *(__half2*)((__half*)C + (size_t)(r0 + 8) * N + cc) = h1;
            } else {
                *(float2*)((float*)C + (size_t)r0 * N + cc)       = make_float2(v00, v01);
                *(float2*)((float*)C + (size_t)(r0 + 8) * N + cc) = make_float2(v10, v11);
            }
        }
    }
}

// ---------------- Ragged flash attention (R12, proven) ----------------
#define AH 72
__global__ void __launch_bounds__(256, 2) attn_kernel(const __half* __restrict__ qkv,
                                                      const int* __restrict__ cu,
                                                      __half* __restrict__ out) {
    extern __shared__ __align__(16) __half sma[];
    __half* Qs  = sma;
    __half* Ksb = sma + 128 * AH;
    __half* Vsb = sma + 128 * AH + 2 * 64 * AH;

    int qt = blockIdx.x, h = blockIdx.y, b = blockIdx.z;
    int base = cu[b];
    int len  = cu[b + 1] - base;
    int q0   = qt * 128;
    if (q0 >= len) return;
    int nq = min(128, len - q0);

    int tid = threadIdx.x;
    int lane = tid & 31, wid = tid >> 5;
    int g = lane >> 2, t4 = lane & 3;
    int qw = wid * 16;

    uint32_t qsu = smem_u32(Qs);
    uint32_t ksu[2] = { smem_u32(Ksb), smem_u32(Ksb + 64 * AH) };
    uint32_t vsu[2] = { smem_u32(Vsb), smem_u32(Vsb + 64 * AH) };

    {
#pragma unroll
        for (int i = 0; i < 4; i++) {
            int idx = tid + i * 256;
            int qi = idx >> 3, dg = idx & 7;
            uint32_t dst = qsu + (uint32_t)(qi * AH + dg * 8) * 2;
            const __half* src = qkv + (size_t)(base + q0 + qi) * 2304 + h * 64 + dg * 8;
            if (qi < nq) CP_ASYNC16(dst, src);
            else         CP_ASYNC16Z(dst, qkv);
        }
    }
    auto issueKV = [&](int t, int s) {
        int kbase = t * 64;
#pragma unroll
        for (int i = 0; i < 2; i++) {
            int idx = tid + i * 256;
            int j = idx >> 3, dg = idx & 7;
            int key = kbase + j;
            uint32_t off = (uint32_t)(j * AH + dg * 8) * 2;
            const __half* src = qkv + (size_t)(base + key) * 2304 + h * 64 + dg * 8;
            if (key < len) {
                CP_ASYNC16(ksu[s] + off, src + 768);
                CP_ASYNC16(vsu[s] + off, src + 1536);
            } else {
                CP_ASYNC16Z(ksu[s] + off, qkv);
                CP_ASYNC16Z(vsu[s] + off, qkv);
            }
        }
        CP_COMMIT();
    };
    issueKV(0, 0);

    float m0 = -1e30f, m1 = -1e30f, l0 = 0.f, l1 = 0.f;
    float oacc[8][4];
#pragma unroll
    for (int nf = 0; nf < 8; nf++)
#pragma unroll
        for (int r = 0; r < 4; r++) oacc[nf][r] = 0.f;

    int ntiles = (len + 63) >> 6;
    for (int t = 0; t < ntiles; t++) {
        CP_WAIT(0);
        __syncthreads();
        if (t + 1 < ntiles) issueKV(t + 1, (t + 1) & 1);

        int st = t & 1;
        const __half* Ks = Ksb + st * 64 * AH;
        int nk = min(64, len - t * 64);

        float sacc[8][4];
#pragma unroll
        for (int nf = 0; nf < 8; nf++)
#pragma unroll
            for (int r = 0; r < 4; r++) sacc[nf][r] = 0.f;
#pragma unroll
        for (int kk = 0; kk < 64; kk += 16) {
            uint32_t af[4];
            af[0] = *(const uint32_t*)&Qs[(qw + g) * AH + kk + 2 * t4];
            af[1] = *(const uint32_t*)&Qs[(qw + g + 8) * AH + kk + 2 * t4];
            af[2] = *(const uint32_t*)&Qs[(qw + g) * AH + kk + 2 * t4 + 8];
            af[3] = *(const uint32_t*)&Qs[(qw + g + 8) * AH + kk + 2 * t4 + 8];
#pragma unroll
            for (int nf = 0; nf < 8; nf++) {
                uint32_t bf[2];
                bf[0] = *(const uint32_t*)&Ks[(nf * 8 + g) * AH + kk + 2 * t4];
                bf[1] = *(const uint32_t*)&Ks[(nf * 8 + g) * AH + kk + 2 * t4 + 8];
                mma_f16(sacc[nf], af, bf);
            }
        }

#pragma unroll
        for (int nf = 0; nf < 8; nf++) {
            sacc[nf][0] *= 0.125f; sacc[nf][1] *= 0.125f;
            sacc[nf][2] *= 0.125f; sacc[nf][3] *= 0.125f;
            int j = nf * 8 + 2 * t4;
            if (j >= nk)     { sacc[nf][0] = -1e30f; sacc[nf][2] = -1e30f; }
            if (j + 1 >= nk) { sacc[nf][1] = -1e30f; sacc[nf][3] = -1e30f; }
        }

        float tm0 = -1e30f, tm1 = -1e30f;
#pragma unroll
        for (int nf = 0; nf < 8; nf++) {
            tm0 = fmaxf(tm0, fmaxf(sacc[nf][0], sacc[nf][1]));
            tm1 = fmaxf(tm1, fmaxf(sacc[nf][2], sacc[nf][3]));
        }
        tm0 = fmaxf(tm0, __shfl_xor_sync(0xffffffffu, tm0, 1));
        tm0 = fmaxf(tm0, __shfl_xor_sync(0xffffffffu, tm0, 2));
        tm1 = fmaxf(tm1, __shfl_xor_sync(0xffffffffu, tm1, 1));
        tm1 = fmaxf(tm1, __shfl_xor_sync(0xffffffffu, tm1, 2));

        float nm0 = fmaxf(m0, tm0), nm1 = fmaxf(m1, tm1);
        float sc0 = __expf(m0 - nm0), sc1 = __expf(m1 - nm1);

        uint32_t ph[8][2];
        float ls0 = 0.f, ls1 = 0.f;
#pragma unroll
        for (int nf = 0; nf < 8; nf++) {
            float p0 = __expf(sacc[nf][0] - nm0);
            float p1 = __expf(sacc[nf][1] - nm0);
            float p2 = __expf(sacc[nf][2] - nm1);
            float p3 = __expf(sacc[nf][3] - nm1);
            ls0 += p0 + p1; ls1 += p2 + p3;
            ph[nf][0] = h2u(p0, p1);
            ph[nf][1] = h2u(p2, p3);
        }
        ls0 += __shfl_xor_sync(0xffffffffu, ls0, 1);
        ls0 += __shfl_xor_sync(0xffffffffu, ls0, 2);
        ls1 += __shfl_xor_sync(0xffffffffu, ls1, 1);
        ls1 += __shfl_xor_sync(0xffffffffu, ls1, 2);
        l0 = l0 * sc0 + ls0;
        l1 = l1 * sc1 + ls1;
        m0 = nm0; m1 = nm1;

#pragma unroll
        for (int nf = 0; nf < 8; nf++) {
            oacc[nf][0] *= sc0; oacc[nf][1] *= sc0;
            oacc[nf][2] *= sc1; oacc[nf][3] *= sc1;
        }

        uint32_t vrow = vsu[st] + (uint32_t)(((lane & 15)) * AH) * 2;
#pragma unroll
        for (int mkb = 0; mkb < 4; mkb++) {
            uint32_t af[4] = { ph[2 * mkb][0], ph[2 * mkb][1],
                               ph[2 * mkb + 1][0], ph[2 * mkb + 1][1] };
            uint32_t rbase = vrow + (uint32_t)(16 * mkb * AH) * 2;
#pragma unroll
            for (int nf = 0; nf < 8; nf++) {
                uint32_t bf[2];
                ldsm_x2_t(bf[0], bf[1], rbase + nf * 16);
                mma_f16(oacc[nf], af, bf);
            }
        }
    }

    float inv0 = 1.0f / l0, inv1 = 1.0f / l1;
    if (qw + g < nq) {
        __half* op = out + (size_t)(base + q0 + qw + g) * D_ + h * 64;
#pragma unroll
        for (int nf = 0; nf < 8; nf++) {
            int cc = nf * 8 + 2 * t4;
            *(__half2*)(op + cc) = __floats2half2_rn(oacc[nf][0] * inv0, oacc[nf][1] * inv0);
        }
    }
    if (qw + g + 8 < nq) {
        __half* op = out + (size_t)(base + q0 + qw + g + 8) * D_ + h * 64;
#pragma unroll
        for (int nf = 0; nf < 8; nf++) {
            int cc = nf * 8 + 2 * t4;
            *(__half2*)(op + cc) = __floats2half2_rn(oacc[nf][2] * inv1, oacc[nf][3] * inv1);
        }
    }
}

// ---------------- host launch ----------------
extern "C" void kernel_launch(void* const* d_in, const int* in_sizes, int n_in,
                              void* d_out, int out_size) {
    const float* x     = (const float*)d_in[0];
    const int*   cu    = (const int*)  d_in[1];
    const float* g1    = (const float*)d_in[2];
    const float* beta1 = (const float*)d_in[3];
    const float* Wqkv  = (const float*)d_in[4];
    const float* bqkv  = (const float*)d_in[5];
    const float* Wo    = (const float*)d_in[6];
    const float* bo    = (const float*)d_in[7];
    const float* g2    = (const float*)d_in[8];
    const float* beta2 = (const float*)d_in[9];
    const float* W1    = (const float*)d_in[10];
    const float* b_fc1 = (const float*)d_in[11];
    const float* W2    = (const float*)d_in[12];
    const float* b_fc2 = (const float*)d_in[13];
    float* out = (float*)d_out;

    int total = in_sizes[0] / D_;   // 6144
    int nb    = in_sizes[1] - 1;    // 8

    __half *xnh, *qkvh, *attnh, *midh, *wqkvTh, *woTh, *w1Th, *w2Th;
    float  *x2;
    cudaGetSymbolAddress((void**)&xnh,    g_xnh);
    cudaGetSymbolAddress((void**)&qkvh,   g_qkvh);
    cudaGetSymbolAddress((void**)&attnh,  g_attnh);
    cudaGetSymbolAddress((void**)&x2,     g_x2);
    cudaGetSymbolAddress((void**)&midh,   g_midh);
    cudaGetSymbolAddress((void**)&wqkvTh, g_WqkvTh);
    cudaGetSymbolAddress((void**)&woTh,   g_WoTh);
    cudaGetSymbolAddress((void**)&w1Th,   g_W1Th);
    cudaGetSymbolAddress((void**)&w2Th,   g_W2Th);

    static cudaStream_t s1 = nullptr, s2 = nullptr;
    static cudaEvent_t evF = nullptr, ev1 = nullptr, ev2 = nullptr;
    if (s1 == nullptr) {
        cudaStreamCreateWithFlags(&s1, cudaStreamNonBlocking);
        cudaStreamCreateWithFlags(&s2, cudaStreamNonBlocking);
        cudaEventCreateWithFlags(&evF, cudaEventDisableTiming);
        cudaEventCreateWithFlags(&ev1, cudaEventDisableTiming);
        cudaEventCreateWithFlags(&ev2, cudaEventDisableTiming);
    }

    int mb = total / 128;
    dim3 tb(32, 8);

    const int GEMM_SMEM = 2 * 2 * STG_H * 2;            // 73728 B
    const int ATTN_SMEM = (128 * AH + 4 * 64 * AH) * 2; // 55296 B
    cudaFuncSetAttribute((const void*)tgemm<0, __half>, cudaFuncAttributeMaxDynamicSharedMemorySize, GEMM_SMEM);
    cudaFuncSetAttribute((const void*)tgemm<1, float>,  cudaFuncAttributeMaxDynamicSharedMemorySize, GEMM_SMEM);
    cudaFuncSetAttribute((const void*)tgemm<2, __half>, cudaFuncAttributeMaxDynamicSharedMemorySize, GEMM_SMEM);
    cudaFuncSetAttribute((const void*)attn_kernel,      cudaFuncAttributeMaxDynamicSharedMemorySize, ATTN_SMEM);

    // fork weight transposes onto side streams
    cudaEventRecord(evF, 0);
    cudaStreamWaitEvent(s1, evF, 0);
    cudaStreamWaitEvent(s2, evF, 0);
    transpose_h<<<dim3(3 * D_ / 32, D_ / 32), tb, 0, s1>>>(Wqkv, wqkvTh, D_, 3 * D_);
    transpose_h<<<dim3(D_ / 32, D_ / 32),     tb, 0, s1>>>(Wo,   woTh,   D_, D_);
    cudaEventRecord(ev1, s1);
    transpose_h<<<dim3(DFF_ / 32, D_ / 32),   tb, 0, s2>>>(W1,   w1Th,   D_, DFF_);
    transpose_h<<<dim3(D_ / 32, DFF_ / 32),   tb, 0, s2>>>(W2,   w2Th,   DFF_, D_);
    cudaEventRecord(ev2, s2);

    // main stream
    ln_kernel<<<total, 256>>>(x, g1, beta1, xnh);
    cudaStreamWaitEvent(0, ev1, 0);
    tgemm<0, __half><<<dim3(3 * D_ / 128, mb), 128, GEMM_SMEM>>>(
        xnh, wqkvTh, bqkv, nullptr, qkvh, total, 3 * D_, D_);
    attn_kernel<<<dim3(SMAX_ / 128, H_, nb), 256, ATTN_SMEM>>>(qkvh, cu, attnh);
    tgemm<1, float><<<dim3(D_ / 128, mb), 128, GEMM_SMEM>>>(
        attnh, woTh, bo, x, x2, total, D_, D_);
    ln_kernel<<<total, 256>>>(x2, g2, beta2, xnh);
    cudaStreamWaitEvent(0, ev2, 0);
    tgemm<2, __half><<<dim3(DFF_ / 128, mb), 128, GEMM_SMEM>>>(
        xnh, w1Th, b_fc1, nullptr, midh, total, DFF_, D_);
    tgemm<1, float><<<dim3(D_ / 128, mb), 128, GEMM_SMEM>>>(
        midh, w2Th, b_fc2, x2, out, total, D_, DFF_);
}

// round 14
// speedup vs baseline: 1.4351x; 1.4351x over previous
#include <cuda_runtime.h>
#include <cuda_fp16.h>
#include <math.h>
#include <stdint.h>

#define D_    768
#define H_    12
#define HD_   64
#define DFF_  3072
#define MAXT  8192
#define SMAX_ 1024

// ---------------- scratch (no allocations allowed) ----------------
__device__ __half g_xnh  [(size_t)MAXT * D_];
__device__ __half g_qkvh [(size_t)MAXT * 3 * D_];
__device__ __half g_attnh[(size_t)MAXT * D_];
__device__ float  g_x2   [(size_t)MAXT * D_];
__device__ __half g_midh [(size_t)MAXT * DFF_];
__device__ __half g_WqkvTh[(size_t)3 * D_ * D_];
__device__ __half g_WoTh  [(size_t)D_ * D_];
__device__ __half g_W1Th  [(size_t)DFF_ * D_];
__device__ __half g_W2Th  [(size_t)D_ * DFF_];

// ---------------- helpers ----------------
__device__ __forceinline__ uint32_t smem_u32(const void* p) {
    uint32_t a;
    asm("{ .reg .u64 t; cvta.to.shared.u64 t, %1; cvt.u32.u64 %0, t; }" : "=r"(a) : "l"(p));
    return a;
}
#define CP_ASYNC16(dst, src) \
    asm volatile("cp.async.cg.shared.global [%0], [%1], 16;" :: "r"(dst), "l"(src) : "memory")
#define CP_ASYNC16Z(dst, src) \
    asm volatile("cp.async.cg.shared.global [%0], [%1], 16, 0;" :: "r"(dst), "l"(src) : "memory")
#define CP_COMMIT() asm volatile("cp.async.commit_group;" ::: "memory")
#define CP_WAIT(n)  asm volatile("cp.async.wait_group %0;" :: "n"(n) : "memory")

__device__ __forceinline__ void mma_f16(float* c, const uint32_t* a, const uint32_t* b) {
    asm volatile(
        "mma.sync.aligned.m16n8k16.row.col.f32.f16.f16.f32 "
        "{%0,%1,%2,%3}, {%4,%5,%6,%7}, {%8,%9}, {%0,%1,%2,%3};"
        : "+f"(c[0]), "+f"(c[1]), "+f"(c[2]), "+f"(c[3])
        : "r"(a[0]), "r"(a[1]), "r"(a[2]), "r"(a[3]), "r"(b[0]), "r"(b[1]));
}
__device__ __forceinline__ void ldsm_x2_t(uint32_t& r0, uint32_t& r1, uint32_t a) {
    asm volatile("ldmatrix.sync.aligned.m8n8.x2.trans.shared.b16 {%0,%1}, [%2];"
                 : "=r"(r0), "=r"(r1) : "r"(a));
}
__device__ __forceinline__ uint32_t h2u(float a, float b) {
    __half2 t = __floats2half2_rn(a, b);
    return *(uint32_t*)&t;
}

// ---------------- transpose + fp16 round ----------------
__global__ void __launch_bounds__(256) transpose_h(const float* __restrict__ W,
                                                   __half* __restrict__ WT,
                                                   int K, int N) {
    __shared__ float tile[32][33];
    int tx = threadIdx.x, ty = threadIdx.y;
    int n0 = blockIdx.x * 32, k0 = blockIdx.y * 32;
#pragma unroll
    for (int i = 0; i < 4; i++)
        tile[ty + 8 * i][tx] = W[(size_t)(k0 + ty + 8 * i) * N + n0 + tx];
    __syncthreads();
#pragma unroll
    for (int i = 0; i < 4; i++)
        WT[(size_t)(n0 + ty + 8 * i) * K + k0 + tx] = __float2half(tile[tx][ty + 8 * i]);
}

// ---------------- LayerNorm (warp-shuffle reduction, fp16 output) ----------------
__global__ void __launch_bounds__(256) ln_kernel(const float* __restrict__ x,
                                                 const float* __restrict__ g,
                                                 const float* __restrict__ be,
                                                 __half* __restrict__ y) {
    int t = blockIdx.x;
    const float* xr = x + (size_t)t * D_;
    __half*      yr = y + (size_t)t * D_;
    int tid  = threadIdx.x;
    int lane = tid & 31, warp = tid >> 5;
    float v0 = xr[tid], v1 = xr[tid + 256], v2 = xr[tid + 512];
    float s  = v0 + v1 + v2;
    float s2 = v0 * v0 + v1 * v1 + v2 * v2;
#pragma unroll
    for (int off = 16; off >= 1; off >>= 1) {
        s  += __shfl_xor_sync(0xffffffffu, s,  off);
        s2 += __shfl_xor_sync(0xffffffffu, s2, off);
    }
    __shared__ float w1[8], w2[8], bc[2];
    if (lane == 0) { w1[warp] = s; w2[warp] = s2; }
    __syncthreads();
    if (warp == 0) {
        float a = (lane < 8) ? w1[lane] : 0.f;
        float b = (lane < 8) ? w2[lane] : 0.f;
#pragma unroll
        for (int off = 4; off >= 1; off >>= 1) {
            a += __shfl_xor_sync(0xffffffffu, a, off);
            b += __shfl_xor_sync(0xffffffffu, b, off);
        }
        if (lane == 0) {
            float mu  = a * (1.0f / D_);
            float var = b * (1.0f / D_) - mu * mu;
            bc[0] = mu;
            bc[1] = rsqrtf(var + 1e-6f);
        }
    }
    __syncthreads();
    float mu = bc[0], r = bc[1];
    yr[tid]       = __float2half((v0 - mu) * r * g[tid]       + be[tid]);
    yr[tid + 256] = __float2half((v1 - mu) * r * g[tid + 256] + be[tid + 256]);
    yr[tid + 512] = __float2half((v2 - mu) * r * g[tid + 512] + be[tid + 512]);
}

// ---------------- fp16 mma.sync GEMM: K-chunk 32, 3-stage ring (proven R12) ------
#define TSH   40
#define STG_H (128 * TSH)
template <int EPI, typename OutT>
__global__ void __launch_bounds__(128) tgemm(const __half* __restrict__ A,
                                             const __half* __restrict__ BT,
                                             const float* __restrict__ bias,
                                             const float* __restrict__ res,
                                             OutT* __restrict__ C,
                                             int M, int N, int K) {
    extern __shared__ __half smh[];
    __half* As = smh;
    __half* Bs = smh + 3 * STG_H;

    int tid = threadIdx.x;
    int lane = tid & 31, wid = tid >> 5;
    int warpM = wid >> 1, warpN = wid & 1;
    int g = lane >> 2, t4 = lane & 3;
    int bm = blockIdx.y * 128, bn = blockIdx.x * 128;

    const __half* gA = A  + (size_t)bm * K;
    const __half* gB = BT + (size_t)bn * K;

    int lrow = tid >> 2;
    int c8   = tid & 3;

    float acc[4][8][4];
#pragma unroll
    for (int mf = 0; mf < 4; mf++)
#pragma unroll
        for (int nf = 0; nf < 8; nf++)
#pragma unroll
            for (int r = 0; r < 4; r++) acc[mf][nf][r] = 0.f;

    uint32_t sA0 = smem_u32(As), sB0 = smem_u32(Bs);
    int nc = K >> 5;

    auto issue = [&](int c, int s) {
        uint32_t sa = sA0 + (uint32_t)s * STG_H * 2;
        uint32_t sb = sB0 + (uint32_t)s * STG_H * 2;
        const __half* a0 = gA + (c << 5) + c8 * 8;
        const __half* b0 = gB + (c << 5) + c8 * 8;
#pragma unroll
        for (int i = 0; i < 4; i++) {
            int row = lrow + 32 * i;
            uint32_t off = (uint32_t)(row * TSH + c8 * 8) * 2;
            CP_ASYNC16(sa + off, a0 + (size_t)row * K);
            CP_ASYNC16(sb + off, b0 + (size_t)row * K);
        }
        CP_COMMIT();
    };

    issue(0, 0);
    if (nc > 1) issue(1, 1);

    for (int c = 0; c < nc; c++) {
        if (c + 1 < nc) { CP_WAIT(1); } else { CP_WAIT(0); }
        __syncthreads();
        if (c + 2 < nc) issue(c + 2, (c + 2) % 3);

        const __half* as = As + (c % 3) * STG_H;
        const __half* bs = Bs + (c % 3) * STG_H;
#pragma unroll
        for (int ko = 0; ko < 32; ko += 16) {
            uint32_t af[4][4];
#pragma unroll
            for (int mf = 0; mf < 4; mf++) {
                int r = warpM * 64 + mf * 16 + g;
                af[mf][0] = *(const uint32_t*)&as[r * TSH + ko + 2 * t4];
                af[mf][1] = *(const uint32_t*)&as[(r + 8) * TSH + ko + 2 * t4];
                af[mf][2] = *(const uint32_t*)&as[r * TSH + ko + 2 * t4 + 8];
                af[mf][3] = *(const uint32_t*)&as[(r + 8) * TSH + ko + 2 * t4 + 8];
            }
            uint32_t bf[8][2];
#pragma unroll
            for (int nf = 0; nf < 8; nf++) {
                int n = warpN * 64 + nf * 8 + g;
                bf[nf][0] = *(const uint32_t*)&bs[n * TSH + ko + 2 * t4];
                bf[nf][1] = *(const uint32_t*)&bs[n * TSH + ko + 2 * t4 + 8];
            }
#pragma unroll
            for (int mf = 0; mf < 4; mf++)
#pragma unroll
                for (int nf = 0; nf < 8; nf++)
                    mma_f16(acc[mf][nf], af[mf], bf[nf]);
        }
    }

#pragma unroll
    for (int mf = 0; mf < 4; mf++) {
        int r0 = bm + warpM * 64 + mf * 16 + g;
#pragma unroll
        for (int nf = 0; nf < 8; nf++) {
            int cc = bn + warpN * 64 + nf * 8 + t4 * 2;
            float b0 = bias[cc], b1 = bias[cc + 1];
            float v00 = acc[mf][nf][0] + b0, v01 = acc[mf][nf][1] + b1;
            float v10 = acc[mf][nf][2] + b0, v11 = acc[mf][nf][3] + b1;
            if (EPI == 1) {
                const float* rp0 = res + (size_t)r0 * N + cc;
                const float* rp1 = res + (size_t)(r0 + 8) * N + cc;
                v00 += rp0[0]; v01 += rp0[1];
                v10 += rp1[0]; v11 += rp1[1];
            }
            if (EPI == 2) {
                v00 = 0.5f * v00 * (1.0f + erff(v00 * 0.70710678118654752f));
                v01 = 0.5f * v01 * (1.0f + erff(v01 * 0.70710678118654752f));
                v10 = 0.5f * v10 * (1.0f + erff(v10 * 0.70710678118654752f));
                v11 = 0.5f * v11 * (1.0f + erff(v11 * 0.70710678118654752f));
            }
            if (sizeof(OutT) == 2) {
                __half2 h0 = __floats2half2_rn(v00, v01);
                __half2 h1 = __floats2half2_rn(v10, v11);
                *(__half2*)((__half*)C + (size_t)r0 * N + cc)       = h0;
                *(__half2*)((__half*)C + (size_t)(r0 + 8) * N + cc) = h1;
            } else {
                *(float2*)((float*)C + (size_t)r0 * N + cc)       = make_float2(v00, v01);
                *(float2*)((float*)C + (size_t)(r0 + 8) * N + cc) = make_float2(v10, v11);
            }
        }
    }
}

// ---------------- Ragged flash attention (R12, proven) ----------------
#define AH 72
__global__ void __launch_bounds__(256, 2) attn_kernel(const __half* __restrict__ qkv,
                                                      const int* __restrict__ cu,
                                                      __half* __restrict__ out) {
    extern __shared__ __align__(16) __half sma[];
    __half* Qs  = sma;
    __half* Ksb = sma + 128 * AH;
    __half* Vsb = sma + 128 * AH + 2 * 64 * AH;

    int qt = blockIdx.x, h = blockIdx.y, b = blockIdx.z;
    int base = cu[b];
    int len  = cu[b + 1] - base;
    int q0   = qt * 128;
    if (q0 >= len) return;
    int nq = min(128, len - q0);

    int tid = threadIdx.x;
    int lane = tid & 31, wid = tid >> 5;
    int g = lane >> 2, t4 = lane & 3;
    int qw = wid * 16;

    uint32_t qsu = smem_u32(Qs);
    uint32_t ksu[2] = { smem_u32(Ksb), smem_u32(Ksb + 64 * AH) };
    uint32_t vsu[2] = { smem_u32(Vsb), smem_u32(Vsb + 64 * AH) };

    {
#pragma unroll
        for (int i = 0; i < 4; i++) {
            int idx = tid + i * 256;
            int qi = idx >> 3, dg = idx & 7;
            uint32_t dst = qsu + (uint32_t)(qi * AH + dg * 8) * 2;
            const __half* src = qkv + (size_t)(base + q0 + qi) * 2304 + h * 64 + dg * 8;
            if (qi < nq) CP_ASYNC16(dst, src);
            else         CP_ASYNC16Z(dst, qkv);
        }
    }
    auto issueKV = [&](int t, int s) {
        int kbase = t * 64;
#pragma unroll
        for (int i = 0; i < 2; i++) {
            int idx = tid + i * 256;
            int j = idx >> 3, dg = idx & 7;
            int key = kbase + j;
            uint32_t off = (uint32_t)(j * AH + dg * 8) * 2;
            const __half* src = qkv + (size_t)(base + key) * 2304 + h * 64 + dg * 8;
            if (key < len) {
                CP_ASYNC16(ksu[s] + off, src + 768);
                CP_ASYNC16(vsu[s] + off, src + 1536);
            } else {
                CP_ASYNC16Z(ksu[s] + off, qkv);
                CP_ASYNC16Z(vsu[s] + off, qkv);
            }
        }
        CP_COMMIT();
    };
    issueKV(0, 0);

    float m0 = -1e30f, m1 = -1e30f, l0 = 0.f, l1 = 0.f;
    float oacc[8][4];
#pragma unroll
    for (int nf = 0; nf < 8; nf++)
#pragma unroll
        for (int r = 0; r < 4; r++) oacc[nf][r] = 0.f;

    int ntiles = (len + 63) >> 6;
    for (int t = 0; t < ntiles; t++) {
        CP_WAIT(0);
        __syncthreads();
        if (t + 1 < ntiles) issueKV(t + 1, (t + 1) & 1);

        int st = t & 1;
        const __half* Ks = Ksb + st * 64 * AH;
        int nk = min(64, len - t * 64);

        float sacc[8][4];
#pragma unroll
        for (int nf = 0; nf < 8; nf++)
#pragma unroll
            for (int r = 0; r < 4; r++) sacc[nf][r] = 0.f;
#pragma unroll
        for (int kk = 0; kk < 64; kk += 16) {
            uint32_t af[4];
            af[0] = *(const uint32_t*)&Qs[(qw + g) * AH + kk + 2 * t4];
            af[1] = *(const uint32_t*)&Qs[(qw + g + 8) * AH + kk + 2 * t4];
            af[2] = *(const uint32_t*)&Qs[(qw + g) * AH + kk + 2 * t4 + 8];
            af[3] = *(const uint32_t*)&Qs[(qw + g + 8) * AH + kk + 2 * t4 + 8];
#pragma unroll
            for (int nf = 0; nf < 8; nf++) {
                uint32_t bf[2];
                bf[0] = *(const uint32_t*)&Ks[(nf * 8 + g) * AH + kk + 2 * t4];
                bf[1] = *(const uint32_t*)&Ks[(nf * 8 + g) * AH + kk + 2 * t4 + 8];
                mma_f16(sacc[nf], af, bf);
            }
        }

#pragma unroll
        for (int nf = 0; nf < 8; nf++) {
            sacc[nf][0] *= 0.125f; sacc[nf][1] *= 0.125f;
            sacc[nf][2] *= 0.125f; sacc[nf][3] *= 0.125f;
            int j = nf * 8 + 2 * t4;
            if (j >= nk)     { sacc[nf][0] = -1e30f; sacc[nf][2] = -1e30f; }
            if (j + 1 >= nk) { sacc[nf][1] = -1e30f; sacc[nf][3] = -1e30f; }
        }

        float tm0 = -1e30f, tm1 = -1e30f;
#pragma unroll
        for (int nf = 0; nf < 8; nf++) {
            tm0 = fmaxf(tm0, fmaxf(sacc[nf][0], sacc[nf][1]));
            tm1 = fmaxf(tm1, fmaxf(sacc[nf][2], sacc[nf][3]));
        }
        tm0 = fmaxf(tm0, __shfl_xor_sync(0xffffffffu, tm0, 1));
        tm0 = fmaxf(tm0, __shfl_xor_sync(0xffffffffu, tm0, 2));
        tm1 = fmaxf(tm1, __shfl_xor_sync(0xffffffffu, tm1, 1));
        tm1 = fmaxf(tm1, __shfl_xor_sync(0xffffffffu, tm1, 2));

        float nm0 = fmaxf(m0, tm0), nm1 = fmaxf(m1, tm1);
        float sc0 = __expf(m0 - nm0), sc1 = __expf(m1 - nm1);

        uint32_t ph[8][2];
        float ls0 = 0.f, ls1 = 0.f;
#pragma unroll
        for (int nf = 0; nf < 8; nf++) {
            float p0 = __expf(sacc[nf][0] - nm0);
            float p1 = __expf(sacc[nf][1] - nm0);
            float p2 = __expf(sacc[nf][2] - nm1);
            float p3 = __expf(sacc[nf][3] - nm1);
            ls0 += p0 + p1; ls1 += p2 + p3;
            ph[nf][0] = h2u(p0, p1);
            ph[nf][1] = h2u(p2, p3);
        }
        ls0 += __shfl_xor_sync(0xffffffffu, ls0, 1);
        ls0 += __shfl_xor_sync(0xffffffffu, ls0, 2);
        ls1 += __shfl_xor_sync(0xffffffffu, ls1, 1);
        ls1 += __shfl_xor_sync(0xffffffffu, ls1, 2);
        l0 = l0 * sc0 + ls0;
        l1 = l1 * sc1 + ls1;
        m0 = nm0; m1 = nm1;

#pragma unroll
        for (int nf = 0; nf < 8; nf++) {
            oacc[nf][0] *= sc0; oacc[nf][1] *= sc0;
            oacc[nf][2] *= sc1; oacc[nf][3] *= sc1;
        }

        uint32_t vrow = vsu[st] + (uint32_t)(((lane & 15)) * AH) * 2;
#pragma unroll
        for (int mkb = 0; mkb < 4; mkb++) {
            uint32_t af[4] = { ph[2 * mkb][0], ph[2 * mkb][1],
                               ph[2 * mkb + 1][0], ph[2 * mkb + 1][1] };
            uint32_t rbase = vrow + (uint32_t)(16 * mkb * AH) * 2;
#pragma unroll
            for (int nf = 0; nf < 8; nf++) {
                uint32_t bf[2];
                ldsm_x2_t(bf[0], bf[1], rbase + nf * 16);
                mma_f16(oacc[nf], af, bf);
            }
        }
    }

    float inv0 = 1.0f / l0, inv1 = 1.0f / l1;
    if (qw + g < nq) {
        __half* op = out + (size_t)(base + q0 + qw + g) * D_ + h * 64;
#pragma unroll
        for (int nf = 0; nf < 8; nf++) {
            int cc = nf * 8 + 2 * t4;
            *(__half2*)(op + cc) = __floats2half2_rn(oacc[nf][0] * inv0, oacc[nf][1] * inv0);
        }
    }
    if (qw + g + 8 < nq) {
        __half* op = out + (size_t)(base + q0 + qw + g + 8) * D_ + h * 64;
#pragma unroll
        for (int nf = 0; nf < 8; nf++) {
            int cc = nf * 8 + 2 * t4;
            *(__half2*)(op + cc) = __floats2half2_rn(oacc[nf][2] * inv1, oacc[nf][3] * inv1);
        }
    }
}

// ---------------- host launch ----------------
extern "C" void kernel_launch(void* const* d_in, const int* in_sizes, int n_in,
                              void* d_out, int out_size) {
    const float* x     = (const float*)d_in[0];
    const int*   cu    = (const int*)  d_in[1];
    const float* g1    = (const float*)d_in[2];
    const float* beta1 = (const float*)d_in[3];
    const float* Wqkv  = (const float*)d_in[4];
    const float* bqkv  = (const float*)d_in[5];
    const float* Wo    = (const float*)d_in[6];
    const float* bo    = (const float*)d_in[7];
    const float* g2    = (const float*)d_in[8];
    const float* beta2 = (const float*)d_in[9];
    const float* W1    = (const float*)d_in[10];
    const float* b_fc1 = (const float*)d_in[11];
    const float* W2    = (const float*)d_in[12];
    const float* b_fc2 = (const float*)d_in[13];
    float* out = (float*)d_out;

    int total = in_sizes[0] / D_;   // 6144
    int nb    = in_sizes[1] - 1;    // 8

    __half *xnh, *qkvh, *attnh, *midh, *wqkvTh, *woTh, *w1Th, *w2Th;
    float  *x2;
    cudaGetSymbolAddress((void**)&xnh,    g_xnh);
    cudaGetSymbolAddress((void**)&qkvh,   g_qkvh);
    cudaGetSymbolAddress((void**)&attnh,  g_attnh);
    cudaGetSymbolAddress((void**)&x2,     g_x2);
    cudaGetSymbolAddress((void**)&midh,   g_midh);
    cudaGetSymbolAddress((void**)&wqkvTh, g_WqkvTh);
    cudaGetSymbolAddress((void**)&woTh,   g_WoTh);
    cudaGetSymbolAddress((void**)&w1Th,   g_W1Th);
    cudaGetSymbolAddress((void**)&w2Th,   g_W2Th);

    static cudaStream_t s1 = nullptr, s2 = nullptr;
    static cudaEvent_t evF = nullptr, evQ = nullptr, evO = nullptr, ev2 = nullptr;
    if (s1 == nullptr) {
        cudaStreamCreateWithFlags(&s1, cudaStreamNonBlocking);
        cudaStreamCreateWithFlags(&s2, cudaStreamNonBlocking);
        cudaEventCreateWithFlags(&evF, cudaEventDisableTiming);
        cudaEventCreateWithFlags(&evQ, cudaEventDisableTiming);
        cudaEventCreateWithFlags(&evO, cudaEventDisableTiming);
        cudaEventCreateWithFlags(&ev2, cudaEventDisableTiming);
    }

    int mb = total / 128;
    dim3 tb(32, 8);

    const int GEMM_SMEM = 2 * 3 * STG_H * 2;            // 61440 B
    const int ATTN_SMEM = (128 * AH + 4 * 64 * AH) * 2; // 55296 B
    cudaFuncSetAttribute((const void*)tgemm<0, __half>, cudaFuncAttributeMaxDynamicSharedMemorySize, GEMM_SMEM);
    cudaFuncSetAttribute((const void*)tgemm<1, float>,  cudaFuncAttributeMaxDynamicSharedMemorySize, GEMM_SMEM);
    cudaFuncSetAttribute((const void*)tgemm<2, __half>, cudaFuncAttributeMaxDynamicSharedMemorySize, GEMM_SMEM);
    cudaFuncSetAttribute((const void*)attn_kernel,      cudaFuncAttributeMaxDynamicSharedMemorySize, ATTN_SMEM);

    // fork weight transposes onto side streams
    cudaEventRecord(evF, 0);
    cudaStreamWaitEvent(s1, evF, 0);
    cudaStreamWaitEvent(s2, evF, 0);
    transpose_h<<<dim3(3 * D_ / 32, D_ / 32), tb, 0, s1>>>(Wqkv, wqkvTh, D_, 3 * D_);
    cudaEventRecord(evQ, s1);                                   // QKV GEMM needs only WqkvT
    transpose_h<<<dim3(D_ / 32, D_ / 32),     tb, 0, s1>>>(Wo,   woTh,   D_, D_);
    cudaEventRecord(evO, s1);
    transpose_h<<<dim3(DFF_ / 32, D_ / 32),   tb, 0, s2>>>(W1,   w1Th,   D_, DFF_);
    transpose_h<<<dim3(D_ / 32, DFF_ / 32),   tb, 0, s2>>>(W2,   w2Th,   DFF_, D_);
    cudaEventRecord(ev2, s2);

    // main stream
    ln_kernel<<<total, 256>>>(x, g1, beta1, xnh);
    cudaStreamWaitEvent(0, evQ, 0);
    tgemm<0, __half><<<dim3(3 * D_ / 128, mb), 128, GEMM_SMEM>>>(
        xnh, wqkvTh, bqkv, nullptr, qkvh, total, 3 * D_, D_);
    attn_kernel<<<dim3(SMAX_ / 128, H_, nb), 256, ATTN_SMEM>>>(qkvh, cu, attnh);
    cudaStreamWaitEvent(0, evO, 0);
    tgemm<1, float><<<dim3(D_ / 128, mb), 128, GEMM_SMEM>>>(
        attnh, woTh, bo, x, x2, total, D_, D_);
    ln_kernel<<<total, 256>>>(x2, g2, beta2, xnh);
    cudaStreamWaitEvent(0, ev2, 0);
    tgemm<2, __half><<<dim3(DFF_ / 128, mb), 128, GEMM_SMEM>>>(
        xnh, w1Th, b_fc1, nullptr, midh, total, DFF_, D_);
    tgemm<1, float><<<dim3(D_ / 128, mb), 128, GEMM_SMEM>>>(
        midh, w2Th, b_fc2, x2, out, total, D_, DFF_);
}